// round 2
// baseline (speedup 1.0000x reference)
#include <cuda_runtime.h>

// Geodesic loss: theta_i = acos(clip((sum(a_i*b_i)-1)*0.5, -1, 1)); out = mean(theta)
// B = in_sizes[0]/9 matrices of 9 contiguous floats each.
//
// HBM-bound streaming reduction. Strategy:
//  - Each block owns 256 matrices = 2304 contiguous floats per input.
//  - Cooperative coalesced float4 load into SMEM (block chunk is 16B-aligned:
//    2304 floats * 4 B = 9216 B per block), loads front-batched for MLP.
//  - Each thread computes one matrix dot from SMEM (stride 9 coprime with 32
//    banks -> conflict-free).
//  - Warp-shuffle + SMEM block reduction, one atomicAdd per block scaled by 1/B.

#define MATS_PER_BLOCK 256
#define FLOATS_PER_BLOCK (MATS_PER_BLOCK * 9)   // 2304
#define VEC4_PER_BLOCK   (FLOATS_PER_BLOCK / 4) // 576

__global__ void geo_init_kernel(float* __restrict__ out) {
    out[0] = 0.0f;
}

__global__ void __launch_bounds__(MATS_PER_BLOCK)
geo_loss_kernel(const float* __restrict__ a,
                const float* __restrict__ b,
                float* __restrict__ out,
                float inv_B) {
    __shared__ float sa[FLOATS_PER_BLOCK];
    __shared__ float sb[FLOATS_PER_BLOCK];
    __shared__ float wsum[MATS_PER_BLOCK / 32];

    const int tid = threadIdx.x;
    const long long base = (long long)blockIdx.x * FLOATS_PER_BLOCK;

    const float4* __restrict__ a4 = reinterpret_cast<const float4*>(a + base);
    const float4* __restrict__ b4 = reinterpret_cast<const float4*>(b + base);
    float4* sa4 = reinterpret_cast<float4*>(sa);
    float4* sb4 = reinterpret_cast<float4*>(sb);

    // Front-batched loads: issue all 6 LDG.128 before any STS (max MLP).
    // 576 = 2*256 + 64: iters 0,1 full; iter 2 covers tid < 64.
    float4 ra0 = a4[tid];
    float4 rb0 = b4[tid];
    float4 ra1 = a4[tid + 256];
    float4 rb1 = b4[tid + 256];
    float4 ra2, rb2;
    if (tid < VEC4_PER_BLOCK - 512) {   // tid < 64
        ra2 = a4[tid + 512];
        rb2 = b4[tid + 512];
    }

    sa4[tid]       = ra0;
    sb4[tid]       = rb0;
    sa4[tid + 256] = ra1;
    sb4[tid + 256] = rb1;
    if (tid < VEC4_PER_BLOCK - 512) {
        sa4[tid + 512] = ra2;
        sb4[tid + 512] = rb2;
    }
    __syncthreads();

    // One matrix per thread: dot of 9 elements.
    const float* pa = sa + tid * 9;
    const float* pb = sb + tid * 9;
    float dot = 0.0f;
    #pragma unroll
    for (int k = 0; k < 9; k++)
        dot = fmaf(pa[k], pb[k], dot);

    float cosv = (dot - 1.0f) * 0.5f;
    cosv = fminf(1.0f, fmaxf(-1.0f, cosv));
    float theta = acosf(cosv);

    // Warp reduction
    #pragma unroll
    for (int off = 16; off > 0; off >>= 1)
        theta += __shfl_down_sync(0xffffffffu, theta, off);
    if ((tid & 31) == 0)
        wsum[tid >> 5] = theta;
    __syncthreads();

    // Final 8-lane reduction in warp 0
    if (tid < 8) {
        float v = wsum[tid];
        #pragma unroll
        for (int off = 4; off > 0; off >>= 1)
            v += __shfl_down_sync(0x000000ffu, v, off);
        if (tid == 0)
            atomicAdd(out, v * inv_B);
    }
}

extern "C" void kernel_launch(void* const* d_in, const int* in_sizes, int n_in,
                              void* d_out, int out_size) {
    const float* a = (const float*)d_in[0];  // pred_rot, B*9 floats
    const float* b = (const float*)d_in[1];  // gt_rot,   B*9 floats
    float* out = (float*)d_out;

    const long long n_elems = in_sizes[0];
    const long long B = n_elems / 9;
    const int blocks = (int)(B / MATS_PER_BLOCK);  // B = 2^21, divides evenly

    geo_init_kernel<<<1, 1>>>(out);
    geo_loss_kernel<<<blocks, MATS_PER_BLOCK>>>(a, b, out, 1.0f / (float)B);
}

// round 3
// speedup vs baseline: 1.0620x; 1.0620x over previous
#include <cuda_runtime.h>
#include <cuda_pipeline.h>

// Geodesic loss: theta_i = acos(clip((sum(a_i*b_i)-1)*0.5, -1, 1)); out = mean(theta)
//
// R3: persistent blocks + 2-stage cp.async (LDGSTS) double buffering.
//  - 888 persistent blocks grid-stride over 8192 chunks of 256 matrices.
//  - While computing chunk i from SMEM stage s, cp.async streams chunk i+1
//    into stage s^1 -> memory requests issue continuously (no load/compute
//    serialization, no block-retire bubbles).
//  - Per-thread theta accumulation across chunks; one atomicAdd per block.

#define THREADS 256
#define MATS 256
#define CHUNK_FLOATS (MATS * 9)       // 2304
#define CHUNK_VEC4 (CHUNK_FLOATS / 4) // 576
#define GRID_BLOCKS 888               // 6 blocks/SM x 148 SMs (SMEM-limited)

__global__ void geo_init_kernel(float* __restrict__ out) {
    out[0] = 0.0f;
}

__device__ __forceinline__ void issue_chunk(float4* sa4, float4* sb4,
                                            const float4* a4, const float4* b4,
                                            int tid) {
    // 576 vec4 per input: indices tid, tid+256, tid+512 (tid<64)
    __pipeline_memcpy_async(&sa4[tid],       &a4[tid],       16);
    __pipeline_memcpy_async(&sb4[tid],       &b4[tid],       16);
    __pipeline_memcpy_async(&sa4[tid + 256], &a4[tid + 256], 16);
    __pipeline_memcpy_async(&sb4[tid + 256], &b4[tid + 256], 16);
    if (tid < CHUNK_VEC4 - 512) {
        __pipeline_memcpy_async(&sa4[tid + 512], &a4[tid + 512], 16);
        __pipeline_memcpy_async(&sb4[tid + 512], &b4[tid + 512], 16);
    }
}

__global__ void __launch_bounds__(THREADS)
geo_loss_kernel(const float* __restrict__ a,
                const float* __restrict__ b,
                float* __restrict__ out,
                float inv_B, int nchunks) {
    __shared__ float sa[2][CHUNK_FLOATS];
    __shared__ float sb[2][CHUNK_FLOATS];
    __shared__ float wsum[THREADS / 32];

    const int tid = threadIdx.x;
    float acc = 0.0f;

    long long c = blockIdx.x;
    if (c < nchunks) {
        issue_chunk((float4*)sa[0], (float4*)sb[0],
                    (const float4*)(a + c * CHUNK_FLOATS),
                    (const float4*)(b + c * CHUNK_FLOATS), tid);
    }
    __pipeline_commit();

    int stage = 0;
    while (c < nchunks) {
        long long cn = c + gridDim.x;
        if (cn < nchunks) {
            issue_chunk((float4*)sa[stage ^ 1], (float4*)sb[stage ^ 1],
                        (const float4*)(a + cn * CHUNK_FLOATS),
                        (const float4*)(b + cn * CHUNK_FLOATS), tid);
            __pipeline_commit();
            __pipeline_wait_prior(1);   // current chunk's group done; next in flight
        } else {
            __pipeline_wait_prior(0);
        }
        __syncthreads();

        // One matrix per thread (SMEM stride 9: coprime with 32 banks).
        const float* pa = sa[stage] + tid * 9;
        const float* pb = sb[stage] + tid * 9;
        float dot = 0.0f;
        #pragma unroll
        for (int k = 0; k < 9; k++)
            dot = fmaf(pa[k], pb[k], dot);

        float cosv = fminf(1.0f, fmaxf(-1.0f, (dot - 1.0f) * 0.5f));
        acc += acosf(cosv);

        __syncthreads();  // compute-reads done before next iter overwrites this stage
        stage ^= 1;
        c = cn;
    }

    // Block reduction of per-thread accumulators.
    #pragma unroll
    for (int off = 16; off > 0; off >>= 1)
        acc += __shfl_down_sync(0xffffffffu, acc, off);
    if ((tid & 31) == 0)
        wsum[tid >> 5] = acc;
    __syncthreads();

    if (tid < 8) {
        float v = wsum[tid];
        #pragma unroll
        for (int off = 4; off > 0; off >>= 1)
            v += __shfl_down_sync(0x000000ffu, v, off);
        if (tid == 0)
            atomicAdd(out, v * inv_B);
    }
}

extern "C" void kernel_launch(void* const* d_in, const int* in_sizes, int n_in,
                              void* d_out, int out_size) {
    const float* a = (const float*)d_in[0];  // pred_rot, B*9 floats
    const float* b = (const float*)d_in[1];  // gt_rot,   B*9 floats
    float* out = (float*)d_out;

    const long long n_elems = in_sizes[0];
    const long long B = n_elems / 9;
    const int nchunks = (int)(B / MATS);     // 8192 (B = 2^21 divides evenly)

    int blocks = GRID_BLOCKS < nchunks ? GRID_BLOCKS : nchunks;

    geo_init_kernel<<<1, 1>>>(out);
    geo_loss_kernel<<<blocks, THREADS>>>(a, b, out, 1.0f / (float)B, nchunks);
}